// round 3
// baseline (speedup 1.0000x reference)
#include <cuda_runtime.h>
#include <math.h>

#define N_NODES 100000
#define N_EDGES 1250000
#define D 64
#define EPSF 1e-8f

// ---------------- scratch (static device memory; no allocation) ----------------
__device__ float g_A[N_NODES * D];      // h @ W1[:, :64].T
__device__ float g_B[N_NODES * D];      // h @ W1[:, 64:].T
__device__ float g_sumA[N_NODES * D];   // seg_sum over dst of A[src]
__device__ float g_maxA[N_NODES * D];   // seg_max over dst of A[src]
__device__ float g_sumwA[N_NODES * D];  // seg_sum over dst of w*A[src]
__device__ float g_h2[N_NODES * D];     // posttrans output (pre-BN)
__device__ float g_absum[N_NODES];      // seg_sum |eig|
__device__ float g_sEig[N_NODES];       // seg_sum eig
__device__ float g_deg[N_NODES];        // degree
__device__ float g_stats[2 * D];        // per-feature sum, sumsq of h2
__device__ float g_scale[D];            // BN scale
__device__ float g_shift[D];            // BN shift

// ---------------- helpers ----------------
__device__ __forceinline__ void atomicMaxF(float* addr, float v) {
    // works for mixed signs given consistent init (-inf)
    if (v >= 0.0f) atomicMax((int*)addr, __float_as_int(v));
    else           atomicMin((unsigned int*)addr, __float_as_uint(v));
}

// ---------------- K0: init scratch ----------------
__global__ void k_init() {
    int i = blockIdx.x * 256 + threadIdx.x;
    if (i < N_NODES * D) {
        g_sumA[i]  = 0.0f;
        g_sumwA[i] = 0.0f;
        g_maxA[i]  = __int_as_float(0xff800000); // -inf
    }
    if (i < N_NODES) {
        g_absum[i] = 0.0f;
        g_sEig[i]  = 0.0f;
        g_deg[i]   = 0.0f;
    }
    if (i < 2 * D) g_stats[i] = 0.0f;
}

// ---------------- K1: node pretrans  A,B = h @ [W1a|W1b].T ----------------
// block: 256 threads, 64 nodes; thread tile 4 nodes x 8 outputs (out dim = 128)
__global__ __launch_bounds__(256) void k_pretrans(const float* __restrict__ h,
                                                  const float* __restrict__ W1) {
    __shared__ __align__(16) float sWt[64][128]; // [k][o] o<64 -> A part, o>=64 -> B part
    __shared__ float sHt[64][64];                // [k][node_local]
    int t = threadIdx.x;
    int base = blockIdx.x * 64;

    for (int idx = t; idx < 64 * 128; idx += 256) {
        int o = idx >> 7, kk = idx & 127;
        float v = W1[idx];            // W1 row-major [o][kk], kk in [0,128)
        if (kk < D) sWt[kk][o] = v;   // A uses first half of the input
        else        sWt[kk - D][o + D] = v;
    }
    for (int idx = t; idx < 64 * 64; idx += 256) {
        int nl = idx >> 6, k = idx & 63;
        int n = base + nl;
        sHt[k][nl] = (n < N_NODES) ? h[n * D + k] : 0.0f;
    }
    __syncthreads();

    int tx = t & 15, ty = t >> 4;
    float acc[4][8];
#pragma unroll
    for (int i = 0; i < 4; i++)
#pragma unroll
        for (int j = 0; j < 8; j++) acc[i][j] = 0.0f;

#pragma unroll 4
    for (int k = 0; k < 64; k++) {
        float4 b0 = *reinterpret_cast<float4*>(&sWt[k][tx * 8]);
        float4 b1v = *reinterpret_cast<float4*>(&sWt[k][tx * 8 + 4]);
#pragma unroll
        for (int i = 0; i < 4; i++) {
            float a = sHt[k][ty * 4 + i];
            acc[i][0] += a * b0.x;  acc[i][1] += a * b0.y;
            acc[i][2] += a * b0.z;  acc[i][3] += a * b0.w;
            acc[i][4] += a * b1v.x; acc[i][5] += a * b1v.y;
            acc[i][6] += a * b1v.z; acc[i][7] += a * b1v.w;
        }
    }

#pragma unroll
    for (int i = 0; i < 4; i++) {
        int n = base + ty * 4 + i;
        if (n >= N_NODES) continue;
        float4 v0 = make_float4(acc[i][0], acc[i][1], acc[i][2], acc[i][3]);
        float4 v1 = make_float4(acc[i][4], acc[i][5], acc[i][6], acc[i][7]);
        if (tx < 8) {
            *reinterpret_cast<float4*>(&g_A[n * D + tx * 8])     = v0;
            *reinterpret_cast<float4*>(&g_A[n * D + tx * 8 + 4]) = v1;
        } else {
            int o = tx * 8 - D;
            *reinterpret_cast<float4*>(&g_B[n * D + o])     = v0;
            *reinterpret_cast<float4*>(&g_B[n * D + o + 4]) = v1;
        }
    }
}

// ---------------- K2: scalar edge pass (absum, sum eig, degree) ----------------
__global__ void k_edge_scalar(const int* __restrict__ dst,
                              const float* __restrict__ eig) {
    int e = blockIdx.x * 256 + threadIdx.x;
    if (e >= N_EDGES) return;
    int d = dst[e];
    float v = eig[e];
    atomicAdd(&g_absum[d], fabsf(v));
    atomicAdd(&g_sEig[d], v);
    atomicAdd(&g_deg[d], 1.0f);
}

// ---------------- K3: vector edge pass (sumA, maxA, sumwA) ----------------
// 16 threads per edge, one float4 lane each
__global__ __launch_bounds__(256) void k_edge_vec(const int* __restrict__ src,
                                                  const int* __restrict__ dst,
                                                  const float* __restrict__ eig) {
    int idx = blockIdx.x * 256 + threadIdx.x;
    if (idx >= N_EDGES * 16) return;
    int e = idx >> 4, c = idx & 15;
    int s = src[e], d = dst[e];
    float w = eig[e] / (g_absum[d] + EPSF);
    float4 a = *reinterpret_cast<const float4*>(&g_A[s * D + c * 4]);
    int off = d * D + c * 4;
    atomicAdd(&g_sumA[off + 0], a.x);
    atomicAdd(&g_sumA[off + 1], a.y);
    atomicAdd(&g_sumA[off + 2], a.z);
    atomicAdd(&g_sumA[off + 3], a.w);
    atomicMaxF(&g_maxA[off + 0], a.x);
    atomicMaxF(&g_maxA[off + 1], a.y);
    atomicMaxF(&g_maxA[off + 2], a.z);
    atomicMaxF(&g_maxA[off + 3], a.w);
    atomicAdd(&g_sumwA[off + 0], w * a.x);
    atomicAdd(&g_sumwA[off + 1], w * a.y);
    atomicAdd(&g_sumwA[off + 2], w * a.z);
    atomicAdd(&g_sumwA[off + 3], w * a.w);
}

// ---------------- K4: node posttrans GEMM + BN partial stats ----------------
// block: 256 threads, 64 nodes; hc[64][256] in smem; W2 staged in 64-k chunks.
// thread tile: 4 nodes x 4 output features.
__global__ __launch_bounds__(256) void k_post(const float* __restrict__ h,
                                              const float* __restrict__ snorm,
                                              const float* __restrict__ W2,
                                              const float* __restrict__ b1,
                                              const float* __restrict__ b2) {
    extern __shared__ float dsm[];
    float* sHC = dsm;                        // [64][256]
    float* sW2 = dsm + 64 * 256;             // [kk][f] chunk, [64][64]
    float* sStats = dsm + 64 * 256 + 64 * 64; // [128]
    int t = threadIdx.x;
    int base = blockIdx.x * 64;
    if (t < 128) sStats[t] = 0.0f;

    int f = t & 63;
    float b1f = __ldg(&b1[f]);
#pragma unroll
    for (int r = 0; r < 16; r++) {
        int nl = (t >> 6) + r * 4;
        int n = base + nl;
        float hv = 0.0f, mean = 0.0f, mx = 0.0f, dir = 0.0f;
        if (n < N_NODES) {
            float deg = g_deg[n];
            float sw = g_sEig[n] / (g_absum[n] + EPSF);  // seg(w)
            int o = n * D + f;
            float Bb = g_B[o] + b1f;
            hv = h[o];
            mean = (g_sumA[o] + deg * Bb) / fmaxf(deg, 1.0f);
            mx = (deg > 0.0f) ? (g_maxA[o] + Bb) : 0.0f;
            dir = fabsf(g_sumwA[o] + sw * Bb - sw * hv);
        }
        float* row = sHC + nl * 256;
        row[f]       = hv;
        row[64 + f]  = mean;
        row[128 + f] = mx;
        row[192 + f] = dir;
    }

    int tx = t & 15, ty = t >> 4;
    float acc[4][4];
#pragma unroll
    for (int i = 0; i < 4; i++)
#pragma unroll
        for (int j = 0; j < 4; j++) acc[i][j] = 0.0f;

    for (int cch = 0; cch < 4; cch++) {
        __syncthreads();  // protect previous chunk reads / phase-1 writes
        for (int idx = t; idx < 4096; idx += 256) {
            int ff = idx >> 6, kk = idx & 63;
            sW2[kk * 64 + ff] = W2[ff * 256 + cch * 64 + kk];
        }
        __syncthreads();
#pragma unroll 4
        for (int kk = 0; kk < 64; kk++) {
            float4 b = *reinterpret_cast<float4*>(&sW2[kk * 64 + tx * 4]);
#pragma unroll
            for (int i = 0; i < 4; i++) {
                float a = sHC[(ty * 4 + i) * 256 + cch * 64 + kk];
                acc[i][0] += a * b.x; acc[i][1] += a * b.y;
                acc[i][2] += a * b.z; acc[i][3] += a * b.w;
            }
        }
    }

    float4 b2v = *reinterpret_cast<const float4*>(&b2[tx * 4]);
#pragma unroll
    for (int i = 0; i < 4; i++) {
        int n = base + ty * 4 + i;
        if (n >= N_NODES) continue;
        float sn = __ldg(&snorm[n]);
        float4 o;
        o.x = (acc[i][0] + b2v.x) * sn;
        o.y = (acc[i][1] + b2v.y) * sn;
        o.z = (acc[i][2] + b2v.z) * sn;
        o.w = (acc[i][3] + b2v.w) * sn;
        *reinterpret_cast<float4*>(&g_h2[n * D + tx * 4]) = o;
        atomicAdd(&sStats[tx * 4 + 0], o.x);
        atomicAdd(&sStats[tx * 4 + 1], o.y);
        atomicAdd(&sStats[tx * 4 + 2], o.z);
        atomicAdd(&sStats[tx * 4 + 3], o.w);
        atomicAdd(&sStats[64 + tx * 4 + 0], o.x * o.x);
        atomicAdd(&sStats[64 + tx * 4 + 1], o.y * o.y);
        atomicAdd(&sStats[64 + tx * 4 + 2], o.z * o.z);
        atomicAdd(&sStats[64 + tx * 4 + 3], o.w * o.w);
    }
    __syncthreads();
    if (t < 128) atomicAdd(&g_stats[t], sStats[t]);
}

// ---------------- K5: BN scale/shift ----------------
__global__ void k_bn(const float* __restrict__ gamma, const float* __restrict__ beta) {
    int f = threadIdx.x;
    if (f < D) {
        const float inv = 1.0f / (float)N_NODES;
        float mu = g_stats[f] * inv;
        float var = g_stats[D + f] * inv - mu * mu;
        float sc = gamma[f] * rsqrtf(var + 1e-5f);
        g_scale[f] = sc;
        g_shift[f] = beta[f] - mu * sc;
    }
}

// ---------------- K6: final elementwise  out = h + relu(h2*scale + shift) ----------------
__global__ void k_final(const float* __restrict__ h, float* __restrict__ out) {
    int i = blockIdx.x * 256 + threadIdx.x;
    if (i < N_NODES * D) {
        int f = i & 63;
        float v = g_h2[i] * g_scale[f] + g_shift[f];
        out[i] = h[i] + fmaxf(v, 0.0f);
    }
}

// ---------------- launch ----------------
extern "C" void kernel_launch(void* const* d_in, const int* in_sizes, int n_in,
                              void* d_out, int out_size) {
    const float* h     = (const float*)d_in[0];
    const float* eig   = (const float*)d_in[1];
    const float* snorm = (const float*)d_in[2];
    const int*   src   = (const int*)d_in[3];
    const int*   dst   = (const int*)d_in[4];
    const float* W1    = (const float*)d_in[5];
    const float* b1    = (const float*)d_in[6];
    const float* W2    = (const float*)d_in[7];
    const float* b2    = (const float*)d_in[8];
    const float* gamma = (const float*)d_in[9];
    const float* beta  = (const float*)d_in[10];
    float* out = (float*)d_out;

    k_init<<<(N_NODES * D + 255) / 256, 256>>>();
    k_pretrans<<<(N_NODES + 63) / 64, 256>>>(h, W1);
    k_edge_scalar<<<(N_EDGES + 255) / 256, 256>>>(dst, eig);
    k_edge_vec<<<(N_EDGES * 16 + 255) / 256, 256>>>(src, dst, eig);

    size_t smem = (size_t)(64 * 256 + 64 * 64 + 2 * D) * sizeof(float);
    cudaFuncSetAttribute(k_post, cudaFuncAttributeMaxDynamicSharedMemorySize, (int)smem);
    k_post<<<(N_NODES + 63) / 64, 256, smem>>>(h, snorm, W2, b1, b2);

    k_bn<<<1, 64>>>(gamma, beta);
    k_final<<<(N_NODES * D + 255) / 256, 256>>>(h, out);
}

// round 6
// speedup vs baseline: 1.5105x; 1.5105x over previous
#include <cuda_runtime.h>
#include <math.h>

#define N_NODES 100000
#define N_EDGES 1250000
#define D 64
#define EPSF 1e-8f

// ---------------- scratch (static device memory; no allocation) ----------------
__device__ float g_A[N_NODES * D];         // h @ W1[:, :64].T
__device__ float g_B[N_NODES * D];         // h @ W1[:, 64:].T
__device__ float g_sumA[N_NODES * D];      // seg_sum over dst of A[src]
__device__ unsigned g_maxA[N_NODES * D];   // seg_max over dst of A[src] (monotonic u32 keys)
__device__ float g_sumwA[N_NODES * D];     // seg_sum over dst of eig*A[src] (RAW, divide later)
__device__ float g_h2[N_NODES * D];        // posttrans output (pre-BN)
__device__ float g_absum[N_NODES];         // seg_sum |eig|
__device__ float g_sEig[N_NODES];          // seg_sum eig
__device__ float g_deg[N_NODES];           // degree
__device__ float g_stats[2 * D];           // per-feature sum, sumsq of h2
__device__ float g_scale[D];               // BN scale
__device__ float g_shift[D];               // BN shift

// Order-preserving float <-> u32 key (unsigned compare == float compare)
__device__ __forceinline__ unsigned fkey(float x) {
    unsigned u = __float_as_uint(x);
    return (u >> 31) ? ~u : (u | 0x80000000u);
}
__device__ __forceinline__ float fdec(unsigned k) {
    unsigned u = (k >> 31) ? (k & 0x7fffffffu) : ~k;
    return __uint_as_float(u);
}
#define NEGINF_KEY 0x007fffffu   // fkey(-inf)

// ---------------- K0: init scratch (v4 stores) ----------------
__global__ __launch_bounds__(256) void k_init() {
    int i = blockIdx.x * 256 + threadIdx.x;      // one 16B vector per thread
    const int NV = (N_NODES * D) / 4;
    if (i < NV) {
        float4 z = make_float4(0.f, 0.f, 0.f, 0.f);
        uint4 m = make_uint4(NEGINF_KEY, NEGINF_KEY, NEGINF_KEY, NEGINF_KEY);
        reinterpret_cast<float4*>(g_sumA)[i]  = z;
        reinterpret_cast<float4*>(g_sumwA)[i] = z;
        reinterpret_cast<uint4*>(g_maxA)[i]   = m;
    }
    if (i < N_NODES) {
        g_absum[i] = 0.0f;
        g_sEig[i]  = 0.0f;
        g_deg[i]   = 0.0f;
    }
    if (i < 2 * D) g_stats[i] = 0.0f;
}

// ---------------- K1: node pretrans  A,B = h @ [W1a|W1b].T ----------------
__global__ __launch_bounds__(256) void k_pretrans(const float* __restrict__ h,
                                                  const float* __restrict__ W1) {
    __shared__ __align__(16) float sWt[64][128]; // [k][o] o<64 -> A part, o>=64 -> B part
    __shared__ float sHt[64][64];                // [k][node_local]
    int t = threadIdx.x;
    int base = blockIdx.x * 64;

    for (int idx = t; idx < 64 * 128; idx += 256) {
        int o = idx >> 7, kk = idx & 127;
        float v = W1[idx];            // W1 row-major [o][kk], kk in [0,128)
        if (kk < D) sWt[kk][o] = v;
        else        sWt[kk - D][o + D] = v;
    }
    for (int idx = t; idx < 64 * 64; idx += 256) {
        int nl = idx >> 6, k = idx & 63;
        int n = base + nl;
        sHt[k][nl] = (n < N_NODES) ? h[n * D + k] : 0.0f;
    }
    __syncthreads();

    int tx = t & 15, ty = t >> 4;
    float acc[4][8];
#pragma unroll
    for (int i = 0; i < 4; i++)
#pragma unroll
        for (int j = 0; j < 8; j++) acc[i][j] = 0.0f;

#pragma unroll 4
    for (int k = 0; k < 64; k++) {
        float4 b0 = *reinterpret_cast<float4*>(&sWt[k][tx * 8]);
        float4 b1v = *reinterpret_cast<float4*>(&sWt[k][tx * 8 + 4]);
#pragma unroll
        for (int i = 0; i < 4; i++) {
            float a = sHt[k][ty * 4 + i];
            acc[i][0] += a * b0.x;  acc[i][1] += a * b0.y;
            acc[i][2] += a * b0.z;  acc[i][3] += a * b0.w;
            acc[i][4] += a * b1v.x; acc[i][5] += a * b1v.y;
            acc[i][6] += a * b1v.z; acc[i][7] += a * b1v.w;
        }
    }

#pragma unroll
    for (int i = 0; i < 4; i++) {
        int n = base + ty * 4 + i;
        if (n >= N_NODES) continue;
        float4 v0 = make_float4(acc[i][0], acc[i][1], acc[i][2], acc[i][3]);
        float4 v1 = make_float4(acc[i][4], acc[i][5], acc[i][6], acc[i][7]);
        if (tx < 8) {
            *reinterpret_cast<float4*>(&g_A[n * D + tx * 8])     = v0;
            *reinterpret_cast<float4*>(&g_A[n * D + tx * 8 + 4]) = v1;
        } else {
            int o = tx * 8 - D;
            *reinterpret_cast<float4*>(&g_B[n * D + o])     = v0;
            *reinterpret_cast<float4*>(&g_B[n * D + o + 4]) = v1;
        }
    }
}

// ---------------- K2: fused edge pass ----------------
// 16 threads per edge, one float4 lane each. c==0 also does the 3 scalar stats.
// sum/sumw: red.global.add.v4.f32 (proven to compile). max: 4 scalar u32-key reds.
__global__ __launch_bounds__(256) void k_edge_vec(const int* __restrict__ src,
                                                  const int* __restrict__ dst,
                                                  const float* __restrict__ eig) {
    long long idx = (long long)blockIdx.x * 256 + threadIdx.x;
    if (idx >= (long long)N_EDGES * 16) return;
    int e = (int)(idx >> 4), c = (int)(idx & 15);
    int s = __ldg(&src[e]), d = __ldg(&dst[e]);
    float w = __ldg(&eig[e]);
    const float4 a = *reinterpret_cast<const float4*>(&g_A[s * D + c * 4]);
    float4 wa = make_float4(w * a.x, w * a.y, w * a.z, w * a.w);
    int off = d * D + c * 4;
    float* pS = &g_sumA[off];
    unsigned* pM = &g_maxA[off];
    float* pW = &g_sumwA[off];
    asm volatile("red.global.add.v4.f32 [%0], {%1,%2,%3,%4};"
                 :: "l"(pS), "f"(a.x), "f"(a.y), "f"(a.z), "f"(a.w) : "memory");
    asm volatile("red.global.add.v4.f32 [%0], {%1,%2,%3,%4};"
                 :: "l"(pW), "f"(wa.x), "f"(wa.y), "f"(wa.z), "f"(wa.w) : "memory");
    atomicMax(pM + 0, fkey(a.x));
    atomicMax(pM + 1, fkey(a.y));
    atomicMax(pM + 2, fkey(a.z));
    atomicMax(pM + 3, fkey(a.w));
    if (c == 0) {
        atomicAdd(&g_absum[d], fabsf(w));
        atomicAdd(&g_sEig[d], w);
        atomicAdd(&g_deg[d], 1.0f);
    }
}

// ---------------- K4: node posttrans GEMM + BN partial stats ----------------
__global__ __launch_bounds__(256) void k_post(const float* __restrict__ h,
                                              const float* __restrict__ snorm,
                                              const float* __restrict__ W2,
                                              const float* __restrict__ b1,
                                              const float* __restrict__ b2) {
    extern __shared__ float dsm[];
    float* sHC = dsm;                         // [64][256]
    float* sW2 = dsm + 64 * 256;              // [kk][f] chunk, [64][64]
    float* sStats = dsm + 64 * 256 + 64 * 64; // [128]
    int t = threadIdx.x;
    int base = blockIdx.x * 64;
    if (t < 128) sStats[t] = 0.0f;

    int f = t & 63;
    float b1f = __ldg(&b1[f]);
#pragma unroll
    for (int r = 0; r < 16; r++) {
        int nl = (t >> 6) + r * 4;
        int n = base + nl;
        float hv = 0.0f, mean = 0.0f, mx = 0.0f, dir = 0.0f;
        if (n < N_NODES) {
            float deg = g_deg[n];
            float ab = g_absum[n] + EPSF;
            float sE = g_sEig[n];
            float sw = sE / ab;                  // seg(w)
            int o = n * D + f;
            float Bb = g_B[o] + b1f;
            hv = h[o];
            mean = (g_sumA[o] + deg * Bb) / fmaxf(deg, 1.0f);
            mx = (deg > 0.0f) ? (fdec(g_maxA[o]) + Bb) : 0.0f;
            // seg(e*w) - seg(w)*h = (seg(eig*A[src]) + sE*Bb)/ab - sw*h
            dir = fabsf((g_sumwA[o] + sE * Bb) / ab - sw * hv);
        }
        float* row = sHC + nl * 256;
        row[f]       = hv;
        row[64 + f]  = mean;
        row[128 + f] = mx;
        row[192 + f] = dir;
    }

    int tx = t & 15, ty = t >> 4;
    float acc[4][4];
#pragma unroll
    for (int i = 0; i < 4; i++)
#pragma unroll
        for (int j = 0; j < 4; j++) acc[i][j] = 0.0f;

    for (int cch = 0; cch < 4; cch++) {
        __syncthreads();
        for (int idx = t; idx < 4096; idx += 256) {
            int ff = idx >> 6, kk = idx & 63;
            sW2[kk * 64 + ff] = W2[ff * 256 + cch * 64 + kk];
        }
        __syncthreads();
#pragma unroll 4
        for (int kk = 0; kk < 64; kk++) {
            float4 b = *reinterpret_cast<float4*>(&sW2[kk * 64 + tx * 4]);
#pragma unroll
            for (int i = 0; i < 4; i++) {
                float a = sHC[(ty * 4 + i) * 256 + cch * 64 + kk];
                acc[i][0] += a * b.x; acc[i][1] += a * b.y;
                acc[i][2] += a * b.z; acc[i][3] += a * b.w;
            }
        }
    }

    float4 b2v = *reinterpret_cast<const float4*>(&b2[tx * 4]);
#pragma unroll
    for (int i = 0; i < 4; i++) {
        int n = base + ty * 4 + i;
        if (n >= N_NODES) continue;
        float sn = __ldg(&snorm[n]);
        float4 o;
        o.x = (acc[i][0] + b2v.x) * sn;
        o.y = (acc[i][1] + b2v.y) * sn;
        o.z = (acc[i][2] + b2v.z) * sn;
        o.w = (acc[i][3] + b2v.w) * sn;
        *reinterpret_cast<float4*>(&g_h2[n * D + tx * 4]) = o;
        atomicAdd(&sStats[tx * 4 + 0], o.x);
        atomicAdd(&sStats[tx * 4 + 1], o.y);
        atomicAdd(&sStats[tx * 4 + 2], o.z);
        atomicAdd(&sStats[tx * 4 + 3], o.w);
        atomicAdd(&sStats[64 + tx * 4 + 0], o.x * o.x);
        atomicAdd(&sStats[64 + tx * 4 + 1], o.y * o.y);
        atomicAdd(&sStats[64 + tx * 4 + 2], o.z * o.z);
        atomicAdd(&sStats[64 + tx * 4 + 3], o.w * o.w);
    }
    __syncthreads();
    if (t < 128) atomicAdd(&g_stats[t], sStats[t]);
}

// ---------------- K5: BN scale/shift ----------------
__global__ void k_bn(const float* __restrict__ gamma, const float* __restrict__ beta) {
    int f = threadIdx.x;
    if (f < D) {
        const float inv = 1.0f / (float)N_NODES;
        float mu = g_stats[f] * inv;
        float var = g_stats[D + f] * inv - mu * mu;
        float sc = gamma[f] * rsqrtf(var + 1e-5f);
        g_scale[f] = sc;
        g_shift[f] = beta[f] - mu * sc;
    }
}

// ---------------- K6: final elementwise  out = h + relu(h2*scale + shift) ----------------
__global__ __launch_bounds__(256) void k_final(const float* __restrict__ h,
                                               float* __restrict__ out) {
    int i = blockIdx.x * 256 + threadIdx.x;   // one float4 per thread
    const int NV = (N_NODES * D) / 4;
    if (i >= NV) return;
    int f4 = (i & 15) * 4;                    // feature offset of this float4
    float4 v = reinterpret_cast<const float4*>(g_h2)[i];
    float4 hv = reinterpret_cast<const float4*>(h)[i];
    float4 sc = *reinterpret_cast<const float4*>(&g_scale[f4]);
    float4 sh = *reinterpret_cast<const float4*>(&g_shift[f4]);
    float4 o;
    o.x = hv.x + fmaxf(v.x * sc.x + sh.x, 0.0f);
    o.y = hv.y + fmaxf(v.y * sc.y + sh.y, 0.0f);
    o.z = hv.z + fmaxf(v.z * sc.z + sh.z, 0.0f);
    o.w = hv.w + fmaxf(v.w * sc.w + sh.w, 0.0f);
    reinterpret_cast<float4*>(out)[i] = o;
}

// ---------------- launch ----------------
extern "C" void kernel_launch(void* const* d_in, const int* in_sizes, int n_in,
                              void* d_out, int out_size) {
    const float* h     = (const float*)d_in[0];
    const float* eig   = (const float*)d_in[1];
    const float* snorm = (const float*)d_in[2];
    const int*   src   = (const int*)d_in[3];
    const int*   dst   = (const int*)d_in[4];
    const float* W1    = (const float*)d_in[5];
    const float* b1    = (const float*)d_in[6];
    const float* W2    = (const float*)d_in[7];
    const float* b2    = (const float*)d_in[8];
    const float* gamma = (const float*)d_in[9];
    const float* beta  = (const float*)d_in[10];
    float* out = (float*)d_out;

    k_init<<<(N_NODES * D / 4 + 255) / 256, 256>>>();
    k_pretrans<<<(N_NODES + 63) / 64, 256>>>(h, W1);

    long long vthreads = (long long)N_EDGES * 16;
    k_edge_vec<<<(int)((vthreads + 255) / 256), 256>>>(src, dst, eig);

    size_t smem = (size_t)(64 * 256 + 64 * 64 + 2 * D) * sizeof(float);
    cudaFuncSetAttribute(k_post, cudaFuncAttributeMaxDynamicSharedMemorySize, (int)smem);
    k_post<<<(N_NODES + 63) / 64, 256, smem>>>(h, snorm, W2, b1, b2);

    k_bn<<<1, 64>>>(gamma, beta);
    k_final<<<(N_NODES * D / 4 + 255) / 256, 256>>>(h, out);
}

// round 8
// speedup vs baseline: 1.5213x; 1.0071x over previous
#include <cuda_runtime.h>
#include <math.h>

#define N_NODES 100000
#define N_EDGES 1250000
#define D 64
#define EPSF 1e-8f

// ---------------- scratch (static device memory; no allocation) ----------------
__device__ float g_A[N_NODES * D];         // h @ W1[:, :64].T
__device__ float g_B[N_NODES * D];         // h @ W1[:, 64:].T
__device__ float g_sumA[N_NODES * D];      // seg_sum over dst of A[src]
__device__ unsigned g_maxA[N_NODES * D];   // seg_max over dst of A[src] (monotonic u32 keys)
__device__ float g_sumwA[N_NODES * D];     // seg_sum over dst of eig*A[src] (RAW, divide later)
__device__ float g_h2[N_NODES * D];        // posttrans output (pre-BN)
__device__ float g_absum[N_NODES];         // seg_sum |eig|
__device__ float g_sEig[N_NODES];          // seg_sum eig
__device__ float g_deg[N_NODES];           // degree
__device__ float g_stats[2 * D];           // per-feature sum, sumsq of h2
__device__ float g_scale[D];               // BN scale
__device__ float g_shift[D];               // BN shift
__device__ float g_W2T[256 * D];           // W2 transposed: [k][o], k in [0,256)

// Order-preserving float <-> u32 key (unsigned compare == float compare)
__device__ __forceinline__ unsigned fkey(float x) {
    unsigned u = __float_as_uint(x);
    return (u >> 31) ? ~u : (u | 0x80000000u);
}
__device__ __forceinline__ float fdec(unsigned k) {
    unsigned u = (k >> 31) ? (k & 0x7fffffffu) : ~k;
    return __uint_as_float(u);
}
#define NEGINF_KEY 0x007fffffu   // fkey(-inf)

// ---------------- K0: init scratch (v4 stores) ----------------
__global__ __launch_bounds__(256) void k_init() {
    int i = blockIdx.x * 256 + threadIdx.x;      // one 16B vector per thread
    const int NV = (N_NODES * D) / 4;
    if (i < NV) {
        float4 z = make_float4(0.f, 0.f, 0.f, 0.f);
        uint4 m = make_uint4(NEGINF_KEY, NEGINF_KEY, NEGINF_KEY, NEGINF_KEY);
        reinterpret_cast<float4*>(g_sumA)[i]  = z;
        reinterpret_cast<float4*>(g_sumwA)[i] = z;
        reinterpret_cast<uint4*>(g_maxA)[i]   = m;
    }
    if (i < N_NODES) {
        g_absum[i] = 0.0f;
        g_sEig[i]  = 0.0f;
        g_deg[i]   = 0.0f;
    }
    if (i < 2 * D) g_stats[i] = 0.0f;
}

// ---------------- K0b: transpose W2 -> g_W2T[k][o] ----------------
__global__ __launch_bounds__(256) void k_w2t(const float* __restrict__ W2) {
    int i = blockIdx.x * 256 + threadIdx.x;   // i = o*256 + k
    if (i < D * 256) {
        int o = i >> 8, k = i & 255;
        g_W2T[k * D + o] = W2[i];
    }
}

// ---------------- K1: node pretrans  A,B = h @ [W1a|W1b].T ----------------
__global__ __launch_bounds__(256) void k_pretrans(const float* __restrict__ h,
                                                  const float* __restrict__ W1) {
    __shared__ __align__(16) float sWt[64][128]; // [k][o] o<64 -> A part, o>=64 -> B part
    __shared__ float sHt[64][64];                // [k][node_local]
    int t = threadIdx.x;
    int base = blockIdx.x * 64;

    for (int idx = t; idx < 64 * 128; idx += 256) {
        int o = idx >> 7, kk = idx & 127;
        float v = W1[idx];            // W1 row-major [o][kk], kk in [0,128)
        if (kk < D) sWt[kk][o] = v;
        else        sWt[kk - D][o + D] = v;
    }
    for (int idx = t; idx < 64 * 64; idx += 256) {
        int nl = idx >> 6, k = idx & 63;
        int n = base + nl;
        sHt[k][nl] = (n < N_NODES) ? h[n * D + k] : 0.0f;
    }
    __syncthreads();

    int tx = t & 15, ty = t >> 4;
    float acc[4][8];
#pragma unroll
    for (int i = 0; i < 4; i++)
#pragma unroll
        for (int j = 0; j < 8; j++) acc[i][j] = 0.0f;

#pragma unroll 4
    for (int k = 0; k < 64; k++) {
        float4 b0 = *reinterpret_cast<float4*>(&sWt[k][tx * 8]);
        float4 b1v = *reinterpret_cast<float4*>(&sWt[k][tx * 8 + 4]);
#pragma unroll
        for (int i = 0; i < 4; i++) {
            float a = sHt[k][ty * 4 + i];
            acc[i][0] += a * b0.x;  acc[i][1] += a * b0.y;
            acc[i][2] += a * b0.z;  acc[i][3] += a * b0.w;
            acc[i][4] += a * b1v.x; acc[i][5] += a * b1v.y;
            acc[i][6] += a * b1v.z; acc[i][7] += a * b1v.w;
        }
    }

#pragma unroll
    for (int i = 0; i < 4; i++) {
        int n = base + ty * 4 + i;
        if (n >= N_NODES) continue;
        float4 v0 = make_float4(acc[i][0], acc[i][1], acc[i][2], acc[i][3]);
        float4 v1 = make_float4(acc[i][4], acc[i][5], acc[i][6], acc[i][7]);
        if (tx < 8) {
            *reinterpret_cast<float4*>(&g_A[n * D + tx * 8])     = v0;
            *reinterpret_cast<float4*>(&g_A[n * D + tx * 8 + 4]) = v1;
        } else {
            int o = tx * 8 - D;
            *reinterpret_cast<float4*>(&g_B[n * D + o])     = v0;
            *reinterpret_cast<float4*>(&g_B[n * D + o + 4]) = v1;
        }
    }
}

// ---------------- K2: fused edge pass ----------------
// 16 threads per edge, one float4 lane each. c==0 also does the 3 scalar stats.
__global__ __launch_bounds__(256) void k_edge_vec(const int* __restrict__ src,
                                                  const int* __restrict__ dst,
                                                  const float* __restrict__ eig) {
    long long idx = (long long)blockIdx.x * 256 + threadIdx.x;
    if (idx >= (long long)N_EDGES * 16) return;
    int e = (int)(idx >> 4), c = (int)(idx & 15);
    int s = __ldg(&src[e]), d = __ldg(&dst[e]);
    float w = __ldg(&eig[e]);
    const float4 a = *reinterpret_cast<const float4*>(&g_A[s * D + c * 4]);
    float4 wa = make_float4(w * a.x, w * a.y, w * a.z, w * a.w);
    int off = d * D + c * 4;
    float* pS = &g_sumA[off];
    unsigned* pM = &g_maxA[off];
    float* pW = &g_sumwA[off];
    asm volatile("red.global.add.v4.f32 [%0], {%1,%2,%3,%4};"
                 :: "l"(pS), "f"(a.x), "f"(a.y), "f"(a.z), "f"(a.w) : "memory");
    asm volatile("red.global.add.v4.f32 [%0], {%1,%2,%3,%4};"
                 :: "l"(pW), "f"(wa.x), "f"(wa.y), "f"(wa.z), "f"(wa.w) : "memory");
    atomicMax(pM + 0, fkey(a.x));
    atomicMax(pM + 1, fkey(a.y));
    atomicMax(pM + 2, fkey(a.z));
    atomicMax(pM + 3, fkey(a.w));
    if (c == 0) {
        atomicAdd(&g_absum[d], fabsf(w));
        atomicAdd(&g_sEig[d], w);
        atomicAdd(&g_deg[d], 1.0f);
    }
}

// ---------------- K4: node posttrans GEMM + BN partial stats ----------------
// 128 threads, 64 nodes/block. hc built chunk-by-chunk ([h|mean|max|dir]),
// GEMM vs pre-transposed W2 chunk. Thread tile: 4 nodes x 8 outputs.
#define HC_S 66   // sHC row stride (4*66=264 words; 264 mod 32 = 8 -> conflict-free a-broadcast)
__global__ __launch_bounds__(128) void k_post(const float* __restrict__ h,
                                              const float* __restrict__ snorm,
                                              const float* __restrict__ b1,
                                              const float* __restrict__ b2) {
    __shared__ float sHC[64 * HC_S];   // [node][k] one chunk
    __shared__ __align__(16) float sW2[64 * 64]; // [k][o] one chunk of W2T
    __shared__ float sStats[2 * D];
    __shared__ float sDeg[64], sAb[64], sSE[64];

    int t = threadIdx.x;
    int base = blockIdx.x * 64;

    if (t < 64) {
        int n = base + t;
        float deg = 0.0f, ab = EPSF, sE = 0.0f;
        if (n < N_NODES) { deg = g_deg[n]; ab = g_absum[n] + EPSF; sE = g_sEig[n]; }
        sDeg[t] = deg; sAb[t] = ab; sSE[t] = sE;
    }
    if (t < 2 * D) sStats[t] = 0.0f;

    int f = t & 63;               // phase-A feature
    int half = t >> 6;            // 0 or 1 (node parity within pass)
    float b1f = __ldg(&b1[f]);

    int tx = t & 7, ty = t >> 3;  // GEMM: 8 outputs x (16 ty * 4 nodes)
    float acc[4][8];
#pragma unroll
    for (int i = 0; i < 4; i++)
#pragma unroll
        for (int j = 0; j < 8; j++) acc[i][j] = 0.0f;

#pragma unroll
    for (int cch = 0; cch < 4; cch++) {
        __syncthreads();   // previous chunk's GEMM reads done
        // stage W2T chunk: 4096 floats, coalesced float4
#pragma unroll
        for (int i = t * 4; i < 4096; i += 512)
            *reinterpret_cast<float4*>(&sW2[i]) =
                *reinterpret_cast<const float4*>(&g_W2T[cch * 4096 + i]);
        // build hc chunk [64 nodes][64 feats]
        for (int r = 0; r < 32; r++) {
            int nl = half + r * 2;
            int n = base + nl;
            float v = 0.0f;
            if (n < N_NODES) {
                int o = n * D + f;
                if (cch == 0) {
                    v = h[o];
                } else if (cch == 1) {
                    float deg = sDeg[nl];
                    v = (g_sumA[o] + deg * (g_B[o] + b1f)) / fmaxf(deg, 1.0f);
                } else if (cch == 2) {
                    v = (sDeg[nl] > 0.0f) ? (fdec(g_maxA[o]) + g_B[o] + b1f) : 0.0f;
                } else {
                    float sE = sSE[nl], ab = sAb[nl];
                    v = fabsf((g_sumwA[o] + sE * (g_B[o] + b1f)) / ab - (sE / ab) * h[o]);
                }
            }
            sHC[nl * HC_S + f] = v;
        }
        __syncthreads();
        // GEMM accumulate over this chunk's 64 k
#pragma unroll 4
        for (int k = 0; k < 64; k++) {
            float4 b0 = *reinterpret_cast<float4*>(&sW2[k * 64 + tx * 8]);
            float4 b1v = *reinterpret_cast<float4*>(&sW2[k * 64 + tx * 8 + 4]);
#pragma unroll
            for (int i = 0; i < 4; i++) {
                float a = sHC[(ty * 4 + i) * HC_S + k];
                acc[i][0] += a * b0.x;  acc[i][1] += a * b0.y;
                acc[i][2] += a * b0.z;  acc[i][3] += a * b0.w;
                acc[i][4] += a * b1v.x; acc[i][5] += a * b1v.y;
                acc[i][6] += a * b1v.z; acc[i][7] += a * b1v.w;
            }
        }
    }

    // epilogue: bias, snorm, write h2, BN partial stats
    float4 bA = *reinterpret_cast<const float4*>(&b2[tx * 8]);
    float4 bB = *reinterpret_cast<const float4*>(&b2[tx * 8 + 4]);
    float s0 = 0, s1 = 0, s2 = 0, s3 = 0, s4 = 0, s5 = 0, s6 = 0, s7 = 0;
    float q0 = 0, q1 = 0, q2 = 0, q3 = 0, q4 = 0, q5 = 0, q6 = 0, q7 = 0;
#pragma unroll
    for (int i = 0; i < 4; i++) {
        int n = base + ty * 4 + i;
        if (n >= N_NODES) continue;
        float sn = __ldg(&snorm[n]);
        float4 oA, oB;
        oA.x = (acc[i][0] + bA.x) * sn; oA.y = (acc[i][1] + bA.y) * sn;
        oA.z = (acc[i][2] + bA.z) * sn; oA.w = (acc[i][3] + bA.w) * sn;
        oB.x = (acc[i][4] + bB.x) * sn; oB.y = (acc[i][5] + bB.y) * sn;
        oB.z = (acc[i][6] + bB.z) * sn; oB.w = (acc[i][7] + bB.w) * sn;
        *reinterpret_cast<float4*>(&g_h2[n * D + tx * 8])     = oA;
        *reinterpret_cast<float4*>(&g_h2[n * D + tx * 8 + 4]) = oB;
        s0 += oA.x; s1 += oA.y; s2 += oA.z; s3 += oA.w;
        s4 += oB.x; s5 += oB.y; s6 += oB.z; s7 += oB.w;
        q0 += oA.x * oA.x; q1 += oA.y * oA.y; q2 += oA.z * oA.z; q3 += oA.w * oA.w;
        q4 += oB.x * oB.x; q5 += oB.y * oB.y; q6 += oB.z * oB.z; q7 += oB.w * oB.w;
    }
    int ob = tx * 8;
    atomicAdd(&sStats[ob + 0], s0); atomicAdd(&sStats[ob + 1], s1);
    atomicAdd(&sStats[ob + 2], s2); atomicAdd(&sStats[ob + 3], s3);
    atomicAdd(&sStats[ob + 4], s4); atomicAdd(&sStats[ob + 5], s5);
    atomicAdd(&sStats[ob + 6], s6); atomicAdd(&sStats[ob + 7], s7);
    atomicAdd(&sStats[D + ob + 0], q0); atomicAdd(&sStats[D + ob + 1], q1);
    atomicAdd(&sStats[D + ob + 2], q2); atomicAdd(&sStats[D + ob + 3], q3);
    atomicAdd(&sStats[D + ob + 4], q4); atomicAdd(&sStats[D + ob + 5], q5);
    atomicAdd(&sStats[D + ob + 6], q6); atomicAdd(&sStats[D + ob + 7], q7);
    __syncthreads();
    if (t < 2 * D) atomicAdd(&g_stats[t], sStats[t]);
}

// ---------------- K5: BN scale/shift ----------------
__global__ void k_bn(const float* __restrict__ gamma, const float* __restrict__ beta) {
    int f = threadIdx.x;
    if (f < D) {
        const float inv = 1.0f / (float)N_NODES;
        float mu = g_stats[f] * inv;
        float var = g_stats[D + f] * inv - mu * mu;
        float sc = gamma[f] * rsqrtf(var + 1e-5f);
        g_scale[f] = sc;
        g_shift[f] = beta[f] - mu * sc;
    }
}

// ---------------- K6: final elementwise  out = h + relu(h2*scale + shift) ----------------
__global__ __launch_bounds__(256) void k_final(const float* __restrict__ h,
                                               float* __restrict__ out) {
    int i = blockIdx.x * 256 + threadIdx.x;   // one float4 per thread
    const int NV = (N_NODES * D) / 4;
    if (i >= NV) return;
    int f4 = (i & 15) * 4;                    // feature offset of this float4
    float4 v = reinterpret_cast<const float4*>(g_h2)[i];
    float4 hv = reinterpret_cast<const float4*>(h)[i];
    float4 sc = *reinterpret_cast<const float4*>(&g_scale[f4]);
    float4 sh = *reinterpret_cast<const float4*>(&g_shift[f4]);
    float4 o;
    o.x = hv.x + fmaxf(v.x * sc.x + sh.x, 0.0f);
    o.y = hv.y + fmaxf(v.y * sc.y + sh.y, 0.0f);
    o.z = hv.z + fmaxf(v.z * sc.z + sh.z, 0.0f);
    o.w = hv.w + fmaxf(v.w * sc.w + sh.w, 0.0f);
    reinterpret_cast<float4*>(out)[i] = o;
}

// ---------------- launch ----------------
extern "C" void kernel_launch(void* const* d_in, const int* in_sizes, int n_in,
                              void* d_out, int out_size) {
    const float* h     = (const float*)d_in[0];
    const float* eig   = (const float*)d_in[1];
    const float* snorm = (const float*)d_in[2];
    const int*   src   = (const int*)d_in[3];
    const int*   dst   = (const int*)d_in[4];
    const float* W1    = (const float*)d_in[5];
    const float* b1    = (const float*)d_in[6];
    const float* W2    = (const float*)d_in[7];
    const float* b2    = (const float*)d_in[8];
    const float* gamma = (const float*)d_in[9];
    const float* beta  = (const float*)d_in[10];
    float* out = (float*)d_out;

    k_init<<<(N_NODES * D / 4 + 255) / 256, 256>>>();
    k_w2t<<<(D * 256 + 255) / 256, 256>>>(W2);
    k_pretrans<<<(N_NODES + 63) / 64, 256>>>(h, W1);

    long long vthreads = (long long)N_EDGES * 16;
    k_edge_vec<<<(int)((vthreads + 255) / 256), 256>>>(src, dst, eig);

    k_post<<<(N_NODES + 63) / 64, 128>>>(h, snorm, b1, b2);

    k_bn<<<1, 64>>>(gamma, beta);
    k_final<<<(N_NODES * D / 4 + 255) / 256, 256>>>(h, out);
}

// round 9
// speedup vs baseline: 2.1455x; 1.4103x over previous
#include <cuda_runtime.h>
#include <math.h>

#define N_NODES 100000
#define N_EDGES 1250000
#define D 64
#define EPSF 1e-8f
#define NEG_INF __int_as_float(0xff800000)

// ---------------- scratch (static device memory; no allocation) ----------------
__device__ float g_A[N_NODES * D];      // h @ W1[:, :64].T
__device__ float g_B[N_NODES * D];      // h @ W1[:, 64:].T
__device__ float g_sumA[N_NODES * D];   // seg_sum over dst of A[src]
__device__ float g_maxA[N_NODES * D];   // seg_max over dst of A[src]
__device__ float g_sumwA[N_NODES * D];  // seg_sum over dst of eig*A[src] (raw)
__device__ float g_h2[N_NODES * D];     // posttrans output (pre-BN)
__device__ float g_absum[N_NODES];      // seg_sum |eig|
__device__ float g_sEig[N_NODES];       // seg_sum eig
__device__ float g_deg[N_NODES];        // degree (float)
__device__ float g_stats[2 * D];        // per-feature sum, sumsq of h2
__device__ float g_scale[D];            // BN scale
__device__ float g_shift[D];            // BN shift
__device__ float g_W2T[256 * D];        // W2 transposed: [k][o]
// CSR machinery
__device__ int g_degi[N_NODES];         // int degree
__device__ int g_start[N_NODES];        // CSR row start (exclusive scan)
__device__ int g_cursor[N_NODES];       // scatter cursors
__device__ int g_eid[N_EDGES];          // edge ids grouped by dst
__device__ int g_bsum[128];             // scan block sums

// ---------------- K0: small init (int degrees + stats) ----------------
__global__ __launch_bounds__(256) void k_small_init() {
    int i = blockIdx.x * 256 + threadIdx.x;
    if (i < N_NODES) g_degi[i] = 0;
    if (i < 2 * D) g_stats[i] = 0.0f;
}

// ---------------- K0b: transpose W2 -> g_W2T[k][o] ----------------
__global__ __launch_bounds__(256) void k_w2t(const float* __restrict__ W2) {
    int i = blockIdx.x * 256 + threadIdx.x;   // i = o*256 + k
    if (i < D * 256) {
        int o = i >> 8, k = i & 255;
        g_W2T[k * D + o] = W2[i];
    }
}

// ---------------- K1: node pretrans  A,B = h @ [W1a|W1b].T ----------------
__global__ __launch_bounds__(256) void k_pretrans(const float* __restrict__ h,
                                                  const float* __restrict__ W1) {
    __shared__ __align__(16) float sWt[64][128]; // [k][o] o<64 -> A, o>=64 -> B
    __shared__ float sHt[64][64];                // [k][node_local]
    int t = threadIdx.x;
    int base = blockIdx.x * 64;

    for (int idx = t; idx < 64 * 128; idx += 256) {
        int o = idx >> 7, kk = idx & 127;
        float v = W1[idx];
        if (kk < D) sWt[kk][o] = v;
        else        sWt[kk - D][o + D] = v;
    }
    for (int idx = t; idx < 64 * 64; idx += 256) {
        int nl = idx >> 6, k = idx & 63;
        int n = base + nl;
        sHt[k][nl] = (n < N_NODES) ? h[n * D + k] : 0.0f;
    }
    __syncthreads();

    int tx = t & 15, ty = t >> 4;
    float acc[4][8];
#pragma unroll
    for (int i = 0; i < 4; i++)
#pragma unroll
        for (int j = 0; j < 8; j++) acc[i][j] = 0.0f;

#pragma unroll 4
    for (int k = 0; k < 64; k++) {
        float4 b0 = *reinterpret_cast<float4*>(&sWt[k][tx * 8]);
        float4 b1v = *reinterpret_cast<float4*>(&sWt[k][tx * 8 + 4]);
#pragma unroll
        for (int i = 0; i < 4; i++) {
            float a = sHt[k][ty * 4 + i];
            acc[i][0] += a * b0.x;  acc[i][1] += a * b0.y;
            acc[i][2] += a * b0.z;  acc[i][3] += a * b0.w;
            acc[i][4] += a * b1v.x; acc[i][5] += a * b1v.y;
            acc[i][6] += a * b1v.z; acc[i][7] += a * b1v.w;
        }
    }

#pragma unroll
    for (int i = 0; i < 4; i++) {
        int n = base + ty * 4 + i;
        if (n >= N_NODES) continue;
        float4 v0 = make_float4(acc[i][0], acc[i][1], acc[i][2], acc[i][3]);
        float4 v1 = make_float4(acc[i][4], acc[i][5], acc[i][6], acc[i][7]);
        if (tx < 8) {
            *reinterpret_cast<float4*>(&g_A[n * D + tx * 8])     = v0;
            *reinterpret_cast<float4*>(&g_A[n * D + tx * 8 + 4]) = v1;
        } else {
            int o = tx * 8 - D;
            *reinterpret_cast<float4*>(&g_B[n * D + o])     = v0;
            *reinterpret_cast<float4*>(&g_B[n * D + o + 4]) = v1;
        }
    }
}

// ---------------- CSR build ----------------
__global__ __launch_bounds__(256) void k_deg(const int* __restrict__ dst) {
    int e = blockIdx.x * 256 + threadIdx.x;
    if (e < N_EDGES) atomicAdd(&g_degi[__ldg(&dst[e])], 1);
}

// level-1 scan: 1024 nodes per block; writes local exclusive + block sums
__global__ __launch_bounds__(1024) void k_scan1() {
    __shared__ int s[1024];
    int t = threadIdx.x;
    int n = blockIdx.x * 1024 + t;
    int v = (n < N_NODES) ? g_degi[n] : 0;
    s[t] = v;
    __syncthreads();
#pragma unroll
    for (int off = 1; off < 1024; off <<= 1) {
        int x = (t >= off) ? s[t - off] : 0;
        __syncthreads();
        s[t] += x;
        __syncthreads();
    }
    if (n < N_NODES) g_start[n] = s[t] - v;   // local exclusive
    if (t == 1023) g_bsum[blockIdx.x] = s[1023];
}

// level-2 scan over 98 block sums (exclusive, in place)
__global__ __launch_bounds__(128) void k_scan2(int nblk) {
    __shared__ int s[128];
    int t = threadIdx.x;
    int v = (t < nblk) ? g_bsum[t] : 0;
    s[t] = v;
    __syncthreads();
#pragma unroll
    for (int off = 1; off < 128; off <<= 1) {
        int x = (t >= off) ? s[t - off] : 0;
        __syncthreads();
        s[t] += x;
        __syncthreads();
    }
    if (t < nblk) g_bsum[t] = s[t] - v;       // exclusive
}

__global__ __launch_bounds__(256) void k_scan3() {
    int n = blockIdx.x * 256 + threadIdx.x;
    if (n < N_NODES) {
        int st = g_start[n] + g_bsum[n >> 10];
        g_start[n] = st;
        g_cursor[n] = st;
    }
}

__global__ __launch_bounds__(256) void k_scatter(const int* __restrict__ dst) {
    int e = blockIdx.x * 256 + threadIdx.x;
    if (e < N_EDGES) {
        int d = __ldg(&dst[e]);
        int pos = atomicAdd(&g_cursor[d], 1);
        g_eid[pos] = e;
    }
}

// ---------------- K2: CSR gather (one warp per node, zero atomics) ----------------
// Two 16-lane groups process alternating edges; register accumulators; shfl combine.
__global__ __launch_bounds__(256) void k_gather(const int* __restrict__ src,
                                                const float* __restrict__ eig) {
    int t = threadIdx.x;
    int n = blockIdx.x * 8 + (t >> 5);     // grid*8 == N_NODES exactly (12500*8)
    int lane = t & 31;
    int grp = lane >> 4;                   // 0/1
    int c = lane & 15;                     // feature quad

    int st = g_start[n];
    int deg = g_degi[n];
    int en = st + deg;

    float4 sum = make_float4(0.f, 0.f, 0.f, 0.f);
    float4 sw  = make_float4(0.f, 0.f, 0.f, 0.f);
    float4 mx  = make_float4(NEG_INF, NEG_INF, NEG_INF, NEG_INF);
    float ab = 0.f, sE = 0.f;

    for (int i = st + grp; i < en; i += 2) {
        int eid = __ldg(&g_eid[i]);
        int s = __ldg(&src[eid]);
        float w = __ldg(&eig[eid]);
        float4 a = *reinterpret_cast<const float4*>(&g_A[s * D + c * 4]);
        sum.x += a.x; sum.y += a.y; sum.z += a.z; sum.w += a.w;
        mx.x = fmaxf(mx.x, a.x); mx.y = fmaxf(mx.y, a.y);
        mx.z = fmaxf(mx.z, a.z); mx.w = fmaxf(mx.w, a.w);
        sw.x += w * a.x; sw.y += w * a.y; sw.z += w * a.z; sw.w += w * a.w;
        ab += fabsf(w); sE += w;
    }

    // combine the two 16-lane groups
    sum.x += __shfl_down_sync(0xffffffffu, sum.x, 16);
    sum.y += __shfl_down_sync(0xffffffffu, sum.y, 16);
    sum.z += __shfl_down_sync(0xffffffffu, sum.z, 16);
    sum.w += __shfl_down_sync(0xffffffffu, sum.w, 16);
    mx.x = fmaxf(mx.x, __shfl_down_sync(0xffffffffu, mx.x, 16));
    mx.y = fmaxf(mx.y, __shfl_down_sync(0xffffffffu, mx.y, 16));
    mx.z = fmaxf(mx.z, __shfl_down_sync(0xffffffffu, mx.z, 16));
    mx.w = fmaxf(mx.w, __shfl_down_sync(0xffffffffu, mx.w, 16));
    sw.x += __shfl_down_sync(0xffffffffu, sw.x, 16);
    sw.y += __shfl_down_sync(0xffffffffu, sw.y, 16);
    sw.z += __shfl_down_sync(0xffffffffu, sw.z, 16);
    sw.w += __shfl_down_sync(0xffffffffu, sw.w, 16);
    ab += __shfl_down_sync(0xffffffffu, ab, 16);
    sE += __shfl_down_sync(0xffffffffu, sE, 16);

    if (grp == 0) {
        int o = n * D + c * 4;
        *reinterpret_cast<float4*>(&g_sumA[o])  = sum;
        *reinterpret_cast<float4*>(&g_maxA[o])  = mx;
        *reinterpret_cast<float4*>(&g_sumwA[o]) = sw;
        if (c == 0) {
            g_deg[n] = (float)deg;
            g_absum[n] = ab;
            g_sEig[n] = sE;
        }
    }
}

// ---------------- K4: node posttrans GEMM + BN partial stats ----------------
#define HC_S 66
__global__ __launch_bounds__(128) void k_post(const float* __restrict__ h,
                                              const float* __restrict__ snorm,
                                              const float* __restrict__ b1,
                                              const float* __restrict__ b2) {
    __shared__ float sHC[64 * HC_S];             // [node][k] one chunk
    __shared__ __align__(16) float sW2[64 * 64]; // [k][o] one chunk of W2T
    __shared__ float sStats[2 * D];
    __shared__ float sDeg[64], sAb[64], sSE[64];

    int t = threadIdx.x;
    int base = blockIdx.x * 64;

    if (t < 64) {
        int n = base + t;
        float deg = 0.0f, ab = EPSF, sE = 0.0f;
        if (n < N_NODES) { deg = g_deg[n]; ab = g_absum[n] + EPSF; sE = g_sEig[n]; }
        sDeg[t] = deg; sAb[t] = ab; sSE[t] = sE;
    }
    if (t < 2 * D) sStats[t] = 0.0f;

    int f = t & 63;
    int half = t >> 6;
    float b1f = __ldg(&b1[f]);

    int tx = t & 7, ty = t >> 3;
    float acc[4][8];
#pragma unroll
    for (int i = 0; i < 4; i++)
#pragma unroll
        for (int j = 0; j < 8; j++) acc[i][j] = 0.0f;

#pragma unroll
    for (int cch = 0; cch < 4; cch++) {
        __syncthreads();
#pragma unroll
        for (int i = t * 4; i < 4096; i += 512)
            *reinterpret_cast<float4*>(&sW2[i]) =
                *reinterpret_cast<const float4*>(&g_W2T[cch * 4096 + i]);
        for (int r = 0; r < 32; r++) {
            int nl = half + r * 2;
            int n = base + nl;
            float v = 0.0f;
            if (n < N_NODES) {
                int o = n * D + f;
                if (cch == 0) {
                    v = h[o];
                } else if (cch == 1) {
                    float deg = sDeg[nl];
                    v = (g_sumA[o] + deg * (g_B[o] + b1f)) / fmaxf(deg, 1.0f);
                } else if (cch == 2) {
                    v = (sDeg[nl] > 0.0f) ? (g_maxA[o] + g_B[o] + b1f) : 0.0f;
                } else {
                    float sE = sSE[nl], ab = sAb[nl];
                    v = fabsf((g_sumwA[o] + sE * (g_B[o] + b1f)) / ab - (sE / ab) * h[o]);
                }
            }
            sHC[nl * HC_S + f] = v;
        }
        __syncthreads();
#pragma unroll 4
        for (int k = 0; k < 64; k++) {
            float4 b0 = *reinterpret_cast<float4*>(&sW2[k * 64 + tx * 8]);
            float4 b1v = *reinterpret_cast<float4*>(&sW2[k * 64 + tx * 8 + 4]);
#pragma unroll
            for (int i = 0; i < 4; i++) {
                float a = sHC[(ty * 4 + i) * HC_S + k];
                acc[i][0] += a * b0.x;  acc[i][1] += a * b0.y;
                acc[i][2] += a * b0.z;  acc[i][3] += a * b0.w;
                acc[i][4] += a * b1v.x; acc[i][5] += a * b1v.y;
                acc[i][6] += a * b1v.z; acc[i][7] += a * b1v.w;
            }
        }
    }

    float4 bA = *reinterpret_cast<const float4*>(&b2[tx * 8]);
    float4 bB = *reinterpret_cast<const float4*>(&b2[tx * 8 + 4]);
    float s0 = 0, s1 = 0, s2 = 0, s3 = 0, s4 = 0, s5 = 0, s6 = 0, s7 = 0;
    float q0 = 0, q1 = 0, q2 = 0, q3 = 0, q4 = 0, q5 = 0, q6 = 0, q7 = 0;
#pragma unroll
    for (int i = 0; i < 4; i++) {
        int n = base + ty * 4 + i;
        if (n >= N_NODES) continue;
        float sn = __ldg(&snorm[n]);
        float4 oA, oB;
        oA.x = (acc[i][0] + bA.x) * sn; oA.y = (acc[i][1] + bA.y) * sn;
        oA.z = (acc[i][2] + bA.z) * sn; oA.w = (acc[i][3] + bA.w) * sn;
        oB.x = (acc[i][4] + bB.x) * sn; oB.y = (acc[i][5] + bB.y) * sn;
        oB.z = (acc[i][6] + bB.z) * sn; oB.w = (acc[i][7] + bB.w) * sn;
        *reinterpret_cast<float4*>(&g_h2[n * D + tx * 8])     = oA;
        *reinterpret_cast<float4*>(&g_h2[n * D + tx * 8 + 4]) = oB;
        s0 += oA.x; s1 += oA.y; s2 += oA.z; s3 += oA.w;
        s4 += oB.x; s5 += oB.y; s6 += oB.z; s7 += oB.w;
        q0 += oA.x * oA.x; q1 += oA.y * oA.y; q2 += oA.z * oA.z; q3 += oA.w * oA.w;
        q4 += oB.x * oB.x; q5 += oB.y * oB.y; q6 += oB.z * oB.z; q7 += oB.w * oB.w;
    }
    int ob = tx * 8;
    atomicAdd(&sStats[ob + 0], s0); atomicAdd(&sStats[ob + 1], s1);
    atomicAdd(&sStats[ob + 2], s2); atomicAdd(&sStats[ob + 3], s3);
    atomicAdd(&sStats[ob + 4], s4); atomicAdd(&sStats[ob + 5], s5);
    atomicAdd(&sStats[ob + 6], s6); atomicAdd(&sStats[ob + 7], s7);
    atomicAdd(&sStats[D + ob + 0], q0); atomicAdd(&sStats[D + ob + 1], q1);
    atomicAdd(&sStats[D + ob + 2], q2); atomicAdd(&sStats[D + ob + 3], q3);
    atomicAdd(&sStats[D + ob + 4], q4); atomicAdd(&sStats[D + ob + 5], q5);
    atomicAdd(&sStats[D + ob + 6], q6); atomicAdd(&sStats[D + ob + 7], q7);
    __syncthreads();
    if (t < 2 * D) atomicAdd(&g_stats[t], sStats[t]);
}

// ---------------- K5: BN scale/shift ----------------
__global__ void k_bn(const float* __restrict__ gamma, const float* __restrict__ beta) {
    int f = threadIdx.x;
    if (f < D) {
        const float inv = 1.0f / (float)N_NODES;
        float mu = g_stats[f] * inv;
        float var = g_stats[D + f] * inv - mu * mu;
        float sc = gamma[f] * rsqrtf(var + 1e-5f);
        g_scale[f] = sc;
        g_shift[f] = beta[f] - mu * sc;
    }
}

// ---------------- K6: final elementwise ----------------
__global__ __launch_bounds__(256) void k_final(const float* __restrict__ h,
                                               float* __restrict__ out) {
    int i = blockIdx.x * 256 + threadIdx.x;
    const int NV = (N_NODES * D) / 4;
    if (i >= NV) return;
    int f4 = (i & 15) * 4;
    float4 v = reinterpret_cast<const float4*>(g_h2)[i];
    float4 hv = reinterpret_cast<const float4*>(h)[i];
    float4 sc = *reinterpret_cast<const float4*>(&g_scale[f4]);
    float4 sh = *reinterpret_cast<const float4*>(&g_shift[f4]);
    float4 o;
    o.x = hv.x + fmaxf(v.x * sc.x + sh.x, 0.0f);
    o.y = hv.y + fmaxf(v.y * sc.y + sh.y, 0.0f);
    o.z = hv.z + fmaxf(v.z * sc.z + sh.z, 0.0f);
    o.w = hv.w + fmaxf(v.w * sc.w + sh.w, 0.0f);
    reinterpret_cast<float4*>(out)[i] = o;
}

// ---------------- launch ----------------
extern "C" void kernel_launch(void* const* d_in, const int* in_sizes, int n_in,
                              void* d_out, int out_size) {
    const float* h     = (const float*)d_in[0];
    const float* eig   = (const float*)d_in[1];
    const float* snorm = (const float*)d_in[2];
    const int*   src   = (const int*)d_in[3];
    const int*   dst   = (const int*)d_in[4];
    const float* W1    = (const float*)d_in[5];
    const float* b1    = (const float*)d_in[6];
    const float* W2    = (const float*)d_in[7];
    const float* b2    = (const float*)d_in[8];
    const float* gamma = (const float*)d_in[9];
    const float* beta  = (const float*)d_in[10];
    float* out = (float*)d_out;

    const int EB = (N_EDGES + 255) / 256;
    const int NB1 = (N_NODES + 1023) / 1024;   // 98

    k_small_init<<<(N_NODES + 255) / 256, 256>>>();
    k_w2t<<<(D * 256 + 255) / 256, 256>>>(W2);
    k_pretrans<<<(N_NODES + 63) / 64, 256>>>(h, W1);

    k_deg<<<EB, 256>>>(dst);
    k_scan1<<<NB1, 1024>>>();
    k_scan2<<<1, 128>>>(NB1);
    k_scan3<<<(N_NODES + 255) / 256, 256>>>();
    k_scatter<<<EB, 256>>>(dst);
    k_gather<<<N_NODES / 8, 256>>>(src, eig);

    k_post<<<(N_NODES + 63) / 64, 128>>>(h, snorm, b1, b2);
    k_bn<<<1, 64>>>(gamma, beta);
    k_final<<<(N_NODES * D / 4 + 255) / 256, 256>>>(h, out);
}

// round 10
// speedup vs baseline: 2.6873x; 1.2525x over previous
#include <cuda_runtime.h>
#include <math.h>

#define N_NODES 100000
#define N_EDGES 1250000
#define D 64
#define EPSF 1e-8f
#define NEG_INF __int_as_float(0xff800000)

// ---------------- scratch (static device memory; no allocation) ----------------
__device__ float g_A[N_NODES * D];      // h @ W1[:, :64].T
__device__ float g_B[N_NODES * D];      // h @ W1[:, 64:].T
__device__ float g_sumA[N_NODES * D];   // seg_sum over dst of A[src]
__device__ float g_maxA[N_NODES * D];   // seg_max over dst of A[src]
__device__ float g_sumwA[N_NODES * D];  // seg_sum over dst of eig*A[src] (raw)
__device__ float g_h2[N_NODES * D];     // posttrans output (pre-BN)
__device__ float g_absum[N_NODES];      // seg_sum |eig|
__device__ float g_sEig[N_NODES];       // seg_sum eig
__device__ float g_deg[N_NODES];        // degree (float)
__device__ float g_stats[2 * D];        // per-feature sum, sumsq of h2
__device__ float g_scale[D];            // BN scale
__device__ float g_shift[D];            // BN shift
__device__ float g_W2T[256 * D];        // W2 transposed: [k][o]
// CSR machinery
__device__ int g_degi[N_NODES];         // int degree
__device__ int g_start[N_NODES];        // CSR row start (exclusive scan)
__device__ int g_cursor[N_NODES];       // scatter cursors
__device__ int2 g_epack[N_EDGES];       // (src, eig bits) grouped by dst
__device__ int g_bsum[128];             // scan block sums

// ---------------- K0: small init (int degrees + stats) ----------------
__global__ __launch_bounds__(256) void k_small_init() {
    int i = blockIdx.x * 256 + threadIdx.x;
    if (i < N_NODES) g_degi[i] = 0;
    if (i < 2 * D) g_stats[i] = 0.0f;
}

// ---------------- K0b: transpose W2 -> g_W2T[k][o] ----------------
__global__ __launch_bounds__(256) void k_w2t(const float* __restrict__ W2) {
    int i = blockIdx.x * 256 + threadIdx.x;   // i = o*256 + k
    if (i < D * 256) {
        int o = i >> 8, k = i & 255;
        g_W2T[k * D + o] = W2[i];
    }
}

// ---------------- K1: node pretrans  A,B = h @ [W1a|W1b].T ----------------
// 256 threads, 128 nodes/block. Thread tile: 8 nodes x 8 outputs (out dim 128).
#define WT_S 132   // sWt row stride (float4-aligned; 4-way STS conflict at worst)
#define HT_S 129   // sHt row stride (conflict-free STS and LDS)
__global__ __launch_bounds__(256) void k_pretrans(const float* __restrict__ h,
                                                  const float* __restrict__ W1) {
    __shared__ __align__(16) float sWt[64 * WT_S]; // [k][o] o<64 -> A, o>=64 -> B
    __shared__ float sHt[64 * HT_S];               // [k][node_local]
    int t = threadIdx.x;
    int base = blockIdx.x * 128;

    for (int idx = t; idx < 64 * 128; idx += 256) {
        int o = idx >> 7, kk = idx & 127;
        float v = W1[idx];                 // W1 row-major [o][kk]
        if (kk < D) sWt[kk * WT_S + o] = v;
        else        sWt[(kk - D) * WT_S + o + D] = v;
    }
    for (int idx = t; idx < 128 * 64; idx += 256) {
        int nl = idx >> 6, k = idx & 63;
        int n = base + nl;
        sHt[k * HT_S + nl] = (n < N_NODES) ? h[n * D + k] : 0.0f;
    }
    __syncthreads();

    int tx = t & 15, ty = t >> 4;   // tx: 8 outputs each (128 total); ty: 8 nodes each (128 total)
    float acc[8][8];
#pragma unroll
    for (int i = 0; i < 8; i++)
#pragma unroll
        for (int j = 0; j < 8; j++) acc[i][j] = 0.0f;

#pragma unroll 2
    for (int k = 0; k < 64; k++) {
        float4 b0 = *reinterpret_cast<float4*>(&sWt[k * WT_S + tx * 8]);
        float4 b1v = *reinterpret_cast<float4*>(&sWt[k * WT_S + tx * 8 + 4]);
#pragma unroll
        for (int i = 0; i < 8; i++) {
            float a = sHt[k * HT_S + ty * 8 + i];
            acc[i][0] += a * b0.x;  acc[i][1] += a * b0.y;
            acc[i][2] += a * b0.z;  acc[i][3] += a * b0.w;
            acc[i][4] += a * b1v.x; acc[i][5] += a * b1v.y;
            acc[i][6] += a * b1v.z; acc[i][7] += a * b1v.w;
        }
    }

#pragma unroll
    for (int i = 0; i < 8; i++) {
        int n = base + ty * 8 + i;
        if (n >= N_NODES) continue;
        float4 v0 = make_float4(acc[i][0], acc[i][1], acc[i][2], acc[i][3]);
        float4 v1 = make_float4(acc[i][4], acc[i][5], acc[i][6], acc[i][7]);
        if (tx < 8) {
            *reinterpret_cast<float4*>(&g_A[n * D + tx * 8])     = v0;
            *reinterpret_cast<float4*>(&g_A[n * D + tx * 8 + 4]) = v1;
        } else {
            int o = tx * 8 - D;
            *reinterpret_cast<float4*>(&g_B[n * D + o])     = v0;
            *reinterpret_cast<float4*>(&g_B[n * D + o + 4]) = v1;
        }
    }
}

// ---------------- CSR build ----------------
__global__ __launch_bounds__(256) void k_deg(const int* __restrict__ dst) {
    int e = blockIdx.x * 256 + threadIdx.x;
    if (e < N_EDGES) atomicAdd(&g_degi[__ldg(&dst[e])], 1);
}

__global__ __launch_bounds__(1024) void k_scan1() {
    __shared__ int s[1024];
    int t = threadIdx.x;
    int n = blockIdx.x * 1024 + t;
    int v = (n < N_NODES) ? g_degi[n] : 0;
    s[t] = v;
    __syncthreads();
#pragma unroll
    for (int off = 1; off < 1024; off <<= 1) {
        int x = (t >= off) ? s[t - off] : 0;
        __syncthreads();
        s[t] += x;
        __syncthreads();
    }
    if (n < N_NODES) g_start[n] = s[t] - v;   // local exclusive
    if (t == 1023) g_bsum[blockIdx.x] = s[1023];
}

__global__ __launch_bounds__(128) void k_scan2(int nblk) {
    __shared__ int s[128];
    int t = threadIdx.x;
    int v = (t < nblk) ? g_bsum[t] : 0;
    s[t] = v;
    __syncthreads();
#pragma unroll
    for (int off = 1; off < 128; off <<= 1) {
        int x = (t >= off) ? s[t - off] : 0;
        __syncthreads();
        s[t] += x;
        __syncthreads();
    }
    if (t < nblk) g_bsum[t] = s[t] - v;       // exclusive
}

__global__ __launch_bounds__(256) void k_scan3() {
    int n = blockIdx.x * 256 + threadIdx.x;
    if (n < N_NODES) {
        int st = g_start[n] + g_bsum[n >> 10];
        g_start[n] = st;
        g_cursor[n] = st;
    }
}

__global__ __launch_bounds__(256) void k_scatter(const int* __restrict__ src,
                                                 const int* __restrict__ dst,
                                                 const float* __restrict__ eig) {
    int e = blockIdx.x * 256 + threadIdx.x;
    if (e < N_EDGES) {
        int d = __ldg(&dst[e]);
        int pos = atomicAdd(&g_cursor[d], 1);
        g_epack[pos] = make_int2(__ldg(&src[e]), __float_as_int(__ldg(&eig[e])));
    }
}

// ---------------- K2: CSR gather (one warp per node, zero atomics) ----------------
__global__ __launch_bounds__(256) void k_gather() {
    int t = threadIdx.x;
    int n = blockIdx.x * 8 + (t >> 5);     // grid*8 == N_NODES exactly (12500*8)
    int lane = t & 31;
    int grp = lane >> 4;                   // 0/1
    int c = lane & 15;                     // feature quad

    int st = g_start[n];
    int deg = g_degi[n];
    int en = st + deg;

    float4 sum = make_float4(0.f, 0.f, 0.f, 0.f);
    float4 sw  = make_float4(0.f, 0.f, 0.f, 0.f);
    float4 mx  = make_float4(NEG_INF, NEG_INF, NEG_INF, NEG_INF);
    float ab = 0.f, sE = 0.f;

    for (int i = st + grp; i < en; i += 2) {
        int2 p = __ldg(&g_epack[i]);
        float w = __int_as_float(p.y);
        float4 a = *reinterpret_cast<const float4*>(&g_A[p.x * D + c * 4]);
        sum.x += a.x; sum.y += a.y; sum.z += a.z; sum.w += a.w;
        mx.x = fmaxf(mx.x, a.x); mx.y = fmaxf(mx.y, a.y);
        mx.z = fmaxf(mx.z, a.z); mx.w = fmaxf(mx.w, a.w);
        sw.x += w * a.x; sw.y += w * a.y; sw.z += w * a.z; sw.w += w * a.w;
        ab += fabsf(w); sE += w;
    }

    sum.x += __shfl_down_sync(0xffffffffu, sum.x, 16);
    sum.y += __shfl_down_sync(0xffffffffu, sum.y, 16);
    sum.z += __shfl_down_sync(0xffffffffu, sum.z, 16);
    sum.w += __shfl_down_sync(0xffffffffu, sum.w, 16);
    mx.x = fmaxf(mx.x, __shfl_down_sync(0xffffffffu, mx.x, 16));
    mx.y = fmaxf(mx.y, __shfl_down_sync(0xffffffffu, mx.y, 16));
    mx.z = fmaxf(mx.z, __shfl_down_sync(0xffffffffu, mx.z, 16));
    mx.w = fmaxf(mx.w, __shfl_down_sync(0xffffffffu, mx.w, 16));
    sw.x += __shfl_down_sync(0xffffffffu, sw.x, 16);
    sw.y += __shfl_down_sync(0xffffffffu, sw.y, 16);
    sw.z += __shfl_down_sync(0xffffffffu, sw.z, 16);
    sw.w += __shfl_down_sync(0xffffffffu, sw.w, 16);
    ab += __shfl_down_sync(0xffffffffu, ab, 16);
    sE += __shfl_down_sync(0xffffffffu, sE, 16);

    if (grp == 0) {
        int o = n * D + c * 4;
        *reinterpret_cast<float4*>(&g_sumA[o])  = sum;
        *reinterpret_cast<float4*>(&g_maxA[o])  = mx;
        *reinterpret_cast<float4*>(&g_sumwA[o]) = sw;
        if (c == 0) {
            g_deg[n] = (float)deg;
            g_absum[n] = ab;
            g_sEig[n] = sE;
        }
    }
}

// ---------------- K4: node posttrans GEMM + BN partial stats ----------------
// 256 threads, 128 nodes/block. hc built chunk-by-chunk ([h|mean|max|dir]).
#define HC_S 66
__global__ __launch_bounds__(256) void k_post(const float* __restrict__ h,
                                              const float* __restrict__ snorm,
                                              const float* __restrict__ b1,
                                              const float* __restrict__ b2) {
    __shared__ float sHC[128 * HC_S];            // [node][k] one chunk (~33.8KB)
    __shared__ __align__(16) float sW2[64 * 64]; // [k][o] one chunk of W2T (16KB)
    __shared__ float sStats[2 * D];
    __shared__ float sDeg[128], sAb[128], sSE[128];

    int t = threadIdx.x;
    int base = blockIdx.x * 128;

    if (t < 128) {
        int n = base + t;
        float deg = 0.0f, ab = EPSF, sE = 0.0f;
        if (n < N_NODES) { deg = g_deg[n]; ab = g_absum[n] + EPSF; sE = g_sEig[n]; }
        sDeg[t] = deg; sAb[t] = ab; sSE[t] = sE;
        sStats[t] = 0.0f;
    }

    int f = t & 63;
    int quarter = t >> 6;          // 0..3
    float b1f = __ldg(&b1[f]);

    int tx = t & 7, ty = t >> 3;   // tx: 8 outputs each; ty: 0..31, 4 nodes each
    float acc[4][8];
#pragma unroll
    for (int i = 0; i < 4; i++)
#pragma unroll
        for (int j = 0; j < 8; j++) acc[i][j] = 0.0f;

#pragma unroll
    for (int cch = 0; cch < 4; cch++) {
        __syncthreads();
#pragma unroll
        for (int i = t * 4; i < 4096; i += 1024)
            *reinterpret_cast<float4*>(&sW2[i]) =
                *reinterpret_cast<const float4*>(&g_W2T[cch * 4096 + i]);
        for (int r = 0; r < 32; r++) {
            int nl = quarter + r * 4;
            int n = base + nl;
            float v = 0.0f;
            if (n < N_NODES) {
                int o = n * D + f;
                if (cch == 0) {
                    v = h[o];
                } else if (cch == 1) {
                    float deg = sDeg[nl];
                    v = (g_sumA[o] + deg * (g_B[o] + b1f)) / fmaxf(deg, 1.0f);
                } else if (cch == 2) {
                    v = (sDeg[nl] > 0.0f) ? (g_maxA[o] + g_B[o] + b1f) : 0.0f;
                } else {
                    float sE = sSE[nl], ab = sAb[nl];
                    v = fabsf((g_sumwA[o] + sE * (g_B[o] + b1f)) / ab - (sE / ab) * h[o]);
                }
            }
            sHC[nl * HC_S + f] = v;
        }
        __syncthreads();
#pragma unroll 4
        for (int k = 0; k < 64; k++) {
            float4 b0 = *reinterpret_cast<float4*>(&sW2[k * 64 + tx * 8]);
            float4 b1v = *reinterpret_cast<float4*>(&sW2[k * 64 + tx * 8 + 4]);
#pragma unroll
            for (int i = 0; i < 4; i++) {
                float a = sHC[(ty * 4 + i) * HC_S + k];
                acc[i][0] += a * b0.x;  acc[i][1] += a * b0.y;
                acc[i][2] += a * b0.z;  acc[i][3] += a * b0.w;
                acc[i][4] += a * b1v.x; acc[i][5] += a * b1v.y;
                acc[i][6] += a * b1v.z; acc[i][7] += a * b1v.w;
            }
        }
    }

    float4 bA = *reinterpret_cast<const float4*>(&b2[tx * 8]);
    float4 bB = *reinterpret_cast<const float4*>(&b2[tx * 8 + 4]);
    float s0 = 0, s1 = 0, s2 = 0, s3 = 0, s4 = 0, s5 = 0, s6 = 0, s7 = 0;
    float q0 = 0, q1 = 0, q2 = 0, q3 = 0, q4 = 0, q5 = 0, q6 = 0, q7 = 0;
#pragma unroll
    for (int i = 0; i < 4; i++) {
        int n = base + ty * 4 + i;
        if (n >= N_NODES) continue;
        float sn = __ldg(&snorm[n]);
        float4 oA, oB;
        oA.x = (acc[i][0] + bA.x) * sn; oA.y = (acc[i][1] + bA.y) * sn;
        oA.z = (acc[i][2] + bA.z) * sn; oA.w = (acc[i][3] + bA.w) * sn;
        oB.x = (acc[i][4] + bB.x) * sn; oB.y = (acc[i][5] + bB.y) * sn;
        oB.z = (acc[i][6] + bB.z) * sn; oB.w = (acc[i][7] + bB.w) * sn;
        *reinterpret_cast<float4*>(&g_h2[n * D + tx * 8])     = oA;
        *reinterpret_cast<float4*>(&g_h2[n * D + tx * 8 + 4]) = oB;
        s0 += oA.x; s1 += oA.y; s2 += oA.z; s3 += oA.w;
        s4 += oB.x; s5 += oB.y; s6 += oB.z; s7 += oB.w;
        q0 += oA.x * oA.x; q1 += oA.y * oA.y; q2 += oA.z * oA.z; q3 += oA.w * oA.w;
        q4 += oB.x * oB.x; q5 += oB.y * oB.y; q6 += oB.z * oB.z; q7 += oB.w * oB.w;
    }
    int ob = tx * 8;
    atomicAdd(&sStats[ob + 0], s0); atomicAdd(&sStats[ob + 1], s1);
    atomicAdd(&sStats[ob + 2], s2); atomicAdd(&sStats[ob + 3], s3);
    atomicAdd(&sStats[ob + 4], s4); atomicAdd(&sStats[ob + 5], s5);
    atomicAdd(&sStats[ob + 6], s6); atomicAdd(&sStats[ob + 7], s7);
    atomicAdd(&sStats[D + ob + 0], q0); atomicAdd(&sStats[D + ob + 1], q1);
    atomicAdd(&sStats[D + ob + 2], q2); atomicAdd(&sStats[D + ob + 3], q3);
    atomicAdd(&sStats[D + ob + 4], q4); atomicAdd(&sStats[D + ob + 5], q5);
    atomicAdd(&sStats[D + ob + 6], q6); atomicAdd(&sStats[D + ob + 7], q7);
    __syncthreads();
    if (t < 2 * D) atomicAdd(&g_stats[t], sStats[t]);
}

// ---------------- K5: BN scale/shift ----------------
__global__ void k_bn(const float* __restrict__ gamma, const float* __restrict__ beta) {
    int f = threadIdx.x;
    if (f < D) {
        const float inv = 1.0f / (float)N_NODES;
        float mu = g_stats[f] * inv;
        float var = g_stats[D + f] * inv - mu * mu;
        float sc = gamma[f] * rsqrtf(var + 1e-5f);
        g_scale[f] = sc;
        g_shift[f] = beta[f] - mu * sc;
    }
}

// ---------------- K6: final elementwise ----------------
__global__ __launch_bounds__(256) void k_final(const float* __restrict__ h,
                                               float* __restrict__ out) {
    int i = blockIdx.x * 256 + threadIdx.x;
    const int NV = (N_NODES * D) / 4;
    if (i >= NV) return;
    int f4 = (i & 15) * 4;
    float4 v = reinterpret_cast<const float4*>(g_h2)[i];
    float4 hv = reinterpret_cast<const float4*>(h)[i];
    float4 sc = *reinterpret_cast<const float4*>(&g_scale[f4]);
    float4 sh = *reinterpret_cast<const float4*>(&g_shift[f4]);
    float4 o;
    o.x = hv.x + fmaxf(v.x * sc.x + sh.x, 0.0f);
    o.y = hv.y + fmaxf(v.y * sc.y + sh.y, 0.0f);
    o.z = hv.z + fmaxf(v.z * sc.z + sh.z, 0.0f);
    o.w = hv.w + fmaxf(v.w * sc.w + sh.w, 0.0f);
    reinterpret_cast<float4*>(out)[i] = o;
}

// ---------------- launch ----------------
extern "C" void kernel_launch(void* const* d_in, const int* in_sizes, int n_in,
                              void* d_out, int out_size) {
    const float* h     = (const float*)d_in[0];
    const float* eig   = (const float*)d_in[1];
    const float* snorm = (const float*)d_in[2];
    const int*   src   = (const int*)d_in[3];
    const int*   dst   = (const int*)d_in[4];
    const float* W1    = (const float*)d_in[5];
    const float* b1    = (const float*)d_in[6];
    const float* W2    = (const float*)d_in[7];
    const float* b2    = (const float*)d_in[8];
    const float* gamma = (const float*)d_in[9];
    const float* beta  = (const float*)d_in[10];
    float* out = (float*)d_out;

    const int EB = (N_EDGES + 255) / 256;
    const int NB1 = (N_NODES + 1023) / 1024;   // 98

    k_small_init<<<(N_NODES + 255) / 256, 256>>>();
    k_w2t<<<(D * 256 + 255) / 256, 256>>>(W2);
    k_deg<<<EB, 256>>>(dst);
    k_pretrans<<<(N_NODES + 127) / 128, 256>>>(h, W1);
    k_scan1<<<NB1, 1024>>>();
    k_scan2<<<1, 128>>>(NB1);
    k_scan3<<<(N_NODES + 255) / 256, 256>>>();
    k_scatter<<<EB, 256>>>(src, dst, eig);
    k_gather<<<N_NODES / 8, 256>>>();

    k_post<<<(N_NODES + 127) / 128, 256>>>(h, snorm, b1, b2);
    k_bn<<<1, 64>>>(gamma, beta);
    k_final<<<(N_NODES * D / 4 + 255) / 256, 256>>>(h, out);
}